// round 3
// baseline (speedup 1.0000x reference)
#include <cuda_runtime.h>
#include <cuda_fp16.h>
#include <cstdint>

#define BB 8
#define SQL 2048
#define SKL 2048
#define DDIM 1024

// ---------------- static device scratch (no allocation allowed) ----------------
__device__ __align__(256) __half g_qh [BB * SQL * DDIM];
__device__ __align__(256) __half g_ql [BB * SQL * DDIM];
__device__ __align__(256) __half g_kh [BB * SKL * DDIM];
__device__ __align__(256) __half g_kl [BB * SKL * DDIM];
__device__ __align__(256) __half g_vh [BB * SKL * DDIM];
__device__ __align__(256) __half g_vl [BB * SKL * DDIM];
__device__ __align__(256) __half g_Wqh[DDIM * DDIM];
__device__ __align__(256) __half g_Wql[DDIM * DDIM];
__device__ __align__(256) __half g_Wkh[DDIM * DDIM];
__device__ __align__(256) __half g_Wkl[DDIM * DDIM];
__device__ __align__(256) __half g_Wvh[DDIM * DDIM];
__device__ __align__(256) __half g_Wvl[DDIM * DDIM];
__device__ __align__(256) __half g_Qph[BB * SQL * DDIM];
__device__ __align__(256) __half g_Qpl[BB * SQL * DDIM];
__device__ __align__(256) __half g_Kph[BB * SKL * DDIM];
__device__ __align__(256) __half g_Kpl[BB * SKL * DDIM];
__device__ __align__(256) __half g_VpT[DDIM * BB * SKL];   // [dv][b*SK + sk]
__device__ __align__(256) float  g_S  [(size_t)BB * SQL * SKL];
__device__ __align__(256) __half g_P  [(size_t)BB * SQL * SKL];

__device__ __forceinline__ uint32_t smem_u32(const void* p) {
    return (uint32_t)__cvta_generic_to_shared(p);
}

// ---------------- fp32 -> (hi,lo) fp16 split convert ----------------
__global__ void cvt_split(const float* __restrict__ x, __half* __restrict__ hi,
                          __half* __restrict__ lo, int n4) {
    int i = blockIdx.x * blockDim.x + threadIdx.x;
    if (i < n4) {
        float4 v = ((const float4*)x)[i];
        __half h0 = __float2half_rn(v.x), h1 = __float2half_rn(v.y);
        __half h2 = __float2half_rn(v.z), h3 = __float2half_rn(v.w);
        __half l0 = __float2half_rn(v.x - __half2float(h0));
        __half l1 = __float2half_rn(v.y - __half2float(h1));
        __half l2 = __float2half_rn(v.z - __half2float(h2));
        __half l3 = __float2half_rn(v.w - __half2float(h3));
        ((__half2*)hi)[2 * i + 0] = __halves2half2(h0, h1);
        ((__half2*)hi)[2 * i + 1] = __halves2half2(h2, h3);
        ((__half2*)lo)[2 * i + 0] = __halves2half2(l0, l1);
        ((__half2*)lo)[2 * i + 1] = __halves2half2(l2, l3);
    }
}

// ---------------- weight transpose + split: W[k][n] f32 -> WT{h,l}[n][k] ----------------
__global__ void wtrans_split(const float* __restrict__ W, __half* __restrict__ WTh,
                             __half* __restrict__ WTl) {
    __shared__ float tile[32][33];
    int kb = blockIdx.x * 32, nb = blockIdx.y * 32;
    int tx = threadIdx.x, ty = threadIdx.y;
#pragma unroll
    for (int r = 0; r < 4; r++)
        tile[ty + 8 * r][tx] = W[(size_t)(kb + ty + 8 * r) * DDIM + nb + tx];
    __syncthreads();
#pragma unroll
    for (int r = 0; r < 4; r++) {
        float x = tile[tx][ty + 8 * r];
        __half h = __float2half_rn(x);
        size_t o = (size_t)(nb + ty + 8 * r) * DDIM + kb + tx;
        WTh[o] = h;
        WTl[o] = __float2half_rn(x - __half2float(h));
    }
}

#define LDS   40      // padded k-stride in halves (32 + 8)
#define OPT   5120    // 128*40 halves per operand tile
#define STG_S (4 * OPT)   // split-kernel stage: Ah,Al,Bh,Bl
#define STG_A 5120
#define STG_T 10240

// =====================================================================
// Split-precision GEMM (3 mma passes): C = (Ah+Al)(Bh+Bl)^T, fp32 acc.
// MODE 0: c += bias, split-store to (C0=hi, C1=lo) fp16
// MODE 1: tanh(c + bias), TRANSPOSED fp16 store to C0 (ldc = rows of C^T)
// MODE 2: fp32 store to C0
// =====================================================================
template <int MODE>
__global__ void __launch_bounds__(256)
gemm_split(const __half* __restrict__ Ah_, const __half* __restrict__ Al_,
           const __half* __restrict__ Bh_, const __half* __restrict__ Bl_,
           void* __restrict__ C0b, void* __restrict__ C1b,
           const float* __restrict__ bias,
           int K, int lda, int ldb, int ldc,
           long sA, long sB, long sC) {
    extern __shared__ __align__(16) __half smem[];

    const __half* Ah = Ah_ + (size_t)blockIdx.z * sA;
    const __half* Al = Al_ + (size_t)blockIdx.z * sA;
    const __half* Bh = Bh_ + (size_t)blockIdx.z * sB;
    const __half* Bl = Bl_ + (size_t)blockIdx.z * sB;

    int tid  = threadIdx.x;
    int lane = tid & 31;
    int warp = tid >> 5;
    int wm = warp & 1;
    int wn = warp >> 1;
    int gm = blockIdx.y * 128;
    int gn = blockIdx.x * 128;
    int nk = K >> 5;

    float c[4][4][4];
#pragma unroll
    for (int i = 0; i < 4; i++)
#pragma unroll
        for (int j = 0; j < 4; j++)
#pragma unroll
            for (int r = 0; r < 4; r++) c[i][j][r] = 0.f;

    auto load_stage = [&](int s, int kt) {
        int k0 = kt * 32;
#pragma unroll
        for (int op = 0; op < 4; op++) {
            const __half* base = (op == 0) ? Ah : (op == 1) ? Al : (op == 2) ? Bh : Bl;
            int ro = (op < 2) ? gm : gn;
            int ld = (op < 2) ? lda : ldb;
            __half* dst0 = smem + s * STG_S + op * OPT;
#pragma unroll
            for (int it = 0; it < 2; it++) {
                int qq = tid + it * 256;
                int r = qq >> 2, cc = qq & 3;
                uint32_t dst = smem_u32(dst0 + r * LDS + cc * 8);
                const __half* src = base + (size_t)(ro + r) * ld + k0 + cc * 8;
                asm volatile("cp.async.cg.shared.global [%0], [%1], 16;\n" ::"r"(dst), "l"(src));
            }
        }
        asm volatile("cp.async.commit_group;\n");
    };

    load_stage(0, 0);

    for (int kt = 0; kt < nk; kt++) {
        if (kt + 1 < nk) {
            load_stage((kt + 1) & 1, kt + 1);
            asm volatile("cp.async.wait_group 1;\n");
        } else {
            asm volatile("cp.async.wait_group 0;\n");
        }
        __syncthreads();

        const __half* sah = smem + (kt & 1) * STG_S;
        const __half* sal = sah + OPT;
        const __half* sbh = sah + 2 * OPT;
        const __half* sbl = sah + 3 * OPT;
#pragma unroll
        for (int ks = 0; ks < 2; ks++) {
            uint32_t ah[4][4], al[4][4], bh[4][2], bl[4][2];
#pragma unroll
            for (int i = 0; i < 4; i++) {
                int roff = (wm * 64 + i * 16 + (lane & 15)) * LDS + ks * 16 + (lane >> 4) * 8;
                uint32_t a0 = smem_u32(sah + roff);
                asm volatile("ldmatrix.sync.aligned.m8n8.x4.shared.b16 {%0,%1,%2,%3}, [%4];"
                             : "=r"(ah[i][0]), "=r"(ah[i][1]), "=r"(ah[i][2]), "=r"(ah[i][3])
                             : "r"(a0));
                uint32_t a1 = smem_u32(sal + roff);
                asm volatile("ldmatrix.sync.aligned.m8n8.x4.shared.b16 {%0,%1,%2,%3}, [%4];"
                             : "=r"(al[i][0]), "=r"(al[i][1]), "=r"(al[i][2]), "=r"(al[i][3])
                             : "r"(a1));
            }
#pragma unroll
            for (int j = 0; j < 4; j++) {
                int roff = (wn * 32 + j * 8 + (lane & 7)) * LDS + ks * 16 + ((lane >> 3) & 1) * 8;
                uint32_t b0 = smem_u32(sbh + roff);
                asm volatile("ldmatrix.sync.aligned.m8n8.x2.shared.b16 {%0,%1}, [%2];"
                             : "=r"(bh[j][0]), "=r"(bh[j][1]) : "r"(b0));
                uint32_t b1 = smem_u32(sbl + roff);
                asm volatile("ldmatrix.sync.aligned.m8n8.x2.shared.b16 {%0,%1}, [%2];"
                             : "=r"(bl[j][0]), "=r"(bl[j][1]) : "r"(b1));
            }
#define MMA4(AA, BB_)                                                                        \
    asm volatile("mma.sync.aligned.m16n8k16.row.col.f32.f16.f16.f32 "                        \
                 "{%0,%1,%2,%3}, {%4,%5,%6,%7}, {%8,%9}, {%0,%1,%2,%3};"                     \
                 : "+f"(c[i][j][0]), "+f"(c[i][j][1]), "+f"(c[i][j][2]), "+f"(c[i][j][3])    \
                 : "r"(AA[i][0]), "r"(AA[i][1]), "r"(AA[i][2]), "r"(AA[i][3]),               \
                   "r"(BB_[j][0]), "r"(BB_[j][1]))
#pragma unroll
            for (int i = 0; i < 4; i++)
#pragma unroll
                for (int j = 0; j < 4; j++) {
                    MMA4(ah, bh);
                    MMA4(ah, bl);
                    MMA4(al, bh);
                }
#undef MMA4
        }
        __syncthreads();
    }

    if (MODE == 0) {
        __half* Chi = (__half*)C0b;
        __half* Clo = (__half*)C1b;
#pragma unroll
        for (int i = 0; i < 4; i++)
#pragma unroll
            for (int j = 0; j < 4; j++) {
                int row = gm + wm * 64 + i * 16 + (lane >> 2);
                int col = gn + wn * 32 + j * 8 + ((lane & 3) << 1);
                float b0 = bias[col], b1 = bias[col + 1];
#pragma unroll
                for (int h = 0; h < 2; h++) {
                    float v0 = c[i][j][2 * h + 0] + b0;
                    float v1 = c[i][j][2 * h + 1] + b1;
                    __half h0 = __float2half_rn(v0), h1 = __float2half_rn(v1);
                    __half l0 = __float2half_rn(v0 - __half2float(h0));
                    __half l1 = __float2half_rn(v1 - __half2float(h1));
                    size_t o = (size_t)(row + 8 * h) * ldc + col;
                    *(__half2*)(Chi + o) = __halves2half2(h0, h1);
                    *(__half2*)(Clo + o) = __halves2half2(l0, l1);
                }
            }
    } else if (MODE == 2) {
        float* C = (float*)C0b + (size_t)blockIdx.z * sC;
#pragma unroll
        for (int i = 0; i < 4; i++)
#pragma unroll
            for (int j = 0; j < 4; j++) {
                int row = gm + wm * 64 + i * 16 + (lane >> 2);
                int col = gn + wn * 32 + j * 8 + ((lane & 3) << 1);
                float2 v0; v0.x = c[i][j][0]; v0.y = c[i][j][1];
                float2 v1; v1.x = c[i][j][2]; v1.y = c[i][j][3];
                *(float2*)(C + (size_t)row * ldc + col) = v0;
                *(float2*)(C + (size_t)(row + 8) * ldc + col) = v1;
            }
    } else {  // MODE 1: tanh + transposed fp16 store via smem staging
        __half* st = smem;  // 128*136 halves = 34816B, fits in dynamic smem
#pragma unroll
        for (int i = 0; i < 4; i++)
#pragma unroll
            for (int j = 0; j < 4; j++) {
                int row = wm * 64 + i * 16 + (lane >> 2);
                int col = wn * 32 + j * 8 + ((lane & 3) << 1);
                float b0 = bias[gn + col], b1 = bias[gn + col + 1];
                st[(col + 0) * 136 + row + 0] = __float2half_rn(tanhf(c[i][j][0] + b0));
                st[(col + 1) * 136 + row + 0] = __float2half_rn(tanhf(c[i][j][1] + b1));
                st[(col + 0) * 136 + row + 8] = __float2half_rn(tanhf(c[i][j][2] + b0));
                st[(col + 1) * 136 + row + 8] = __float2half_rn(tanhf(c[i][j][3] + b1));
            }
        __syncthreads();
        __half* C = (__half*)C0b;
        for (int qq = tid; qq < 128 * 128; qq += 256) {
            int n = qq >> 7, m = qq & 127;
            C[(size_t)(gn + n) * ldc + gm + m] = st[n * 136 + m];
        }
    }
}

// =====================================================================
// Plain fp16 GEMM (single pass) for P·V. MODE 2: fp32 store.
// =====================================================================
template <int MODE>
__global__ void __launch_bounds__(256)
gemm_f16(const __half* __restrict__ Ab, const __half* __restrict__ Btb,
         void* __restrict__ Cb, int K, int lda, int ldb, int ldc,
         long sA, long sB, long sC) {
    __shared__ __align__(16) __half smem[2 * STG_T];

    const __half* A  = Ab  + (size_t)blockIdx.z * sA;
    const __half* Bt = Btb + (size_t)blockIdx.z * sB;

    int tid  = threadIdx.x;
    int lane = tid & 31;
    int warp = tid >> 5;
    int wm = warp & 1;
    int wn = warp >> 1;
    int gm = blockIdx.y * 128;
    int gn = blockIdx.x * 128;
    int nk = K >> 5;

    float c[4][4][4];
#pragma unroll
    for (int i = 0; i < 4; i++)
#pragma unroll
        for (int j = 0; j < 4; j++)
#pragma unroll
            for (int r = 0; r < 4; r++) c[i][j][r] = 0.f;

    auto load_stage = [&](int s, int kt) {
        __half* sa = smem + s * STG_T;
        __half* sb = sa + STG_A;
        int k0 = kt * 32;
#pragma unroll
        for (int it = 0; it < 2; it++) {
            int qq = tid + it * 256;
            int r = qq >> 2, cc = qq & 3;
            uint32_t dst = smem_u32(sa + r * LDS + cc * 8);
            const __half* src = A + (size_t)(gm + r) * lda + k0 + cc * 8;
            asm volatile("cp.async.cg.shared.global [%0], [%1], 16;\n" ::"r"(dst), "l"(src));
        }
#pragma unroll
        for (int it = 0; it < 2; it++) {
            int qq = tid + it * 256;
            int r = qq >> 2, cc = qq & 3;
            uint32_t dst = smem_u32(sb + r * LDS + cc * 8);
            const __half* src = Bt + (size_t)(gn + r) * ldb + k0 + cc * 8;
            asm volatile("cp.async.cg.shared.global [%0], [%1], 16;\n" ::"r"(dst), "l"(src));
        }
        asm volatile("cp.async.commit_group;\n");
    };

    load_stage(0, 0);

    for (int kt = 0; kt < nk; kt++) {
        if (kt + 1 < nk) {
            load_stage((kt + 1) & 1, kt + 1);
            asm volatile("cp.async.wait_group 1;\n");
        } else {
            asm volatile("cp.async.wait_group 0;\n");
        }
        __syncthreads();

        const __half* sa = smem + (kt & 1) * STG_T;
        const __half* sb = sa + STG_A;
#pragma unroll
        for (int ks = 0; ks < 2; ks++) {
            uint32_t a[4][4], b[4][2];
#pragma unroll
            for (int i = 0; i < 4; i++) {
                uint32_t addr = smem_u32(sa + (size_t)(wm * 64 + i * 16 + (lane & 15)) * LDS +
                                         ks * 16 + (lane >> 4) * 8);
                asm volatile("ldmatrix.sync.aligned.m8n8.x4.shared.b16 {%0,%1,%2,%3}, [%4];"
                             : "=r"(a[i][0]), "=r"(a[i][1]), "=r"(a[i][2]), "=r"(a[i][3])
                             : "r"(addr));
            }
#pragma unroll
            for (int j = 0; j < 4; j++) {
                uint32_t addr = smem_u32(sb + (size_t)(wn * 32 + j * 8 + (lane & 7)) * LDS +
                                         ks * 16 + ((lane >> 3) & 1) * 8);
                asm volatile("ldmatrix.sync.aligned.m8n8.x2.shared.b16 {%0,%1}, [%2];"
                             : "=r"(b[j][0]), "=r"(b[j][1])
                             : "r"(addr));
            }
#pragma unroll
            for (int i = 0; i < 4; i++)
#pragma unroll
                for (int j = 0; j < 4; j++) {
                    asm volatile(
                        "mma.sync.aligned.m16n8k16.row.col.f32.f16.f16.f32 "
                        "{%0,%1,%2,%3}, {%4,%5,%6,%7}, {%8,%9}, {%0,%1,%2,%3};"
                        : "+f"(c[i][j][0]), "+f"(c[i][j][1]), "+f"(c[i][j][2]), "+f"(c[i][j][3])
                        : "r"(a[i][0]), "r"(a[i][1]), "r"(a[i][2]), "r"(a[i][3]),
                          "r"(b[j][0]), "r"(b[j][1]));
                }
        }
        __syncthreads();
    }

    if (MODE == 2) {
        float* C = (float*)Cb + (size_t)blockIdx.z * sC;
#pragma unroll
        for (int i = 0; i < 4; i++)
#pragma unroll
            for (int j = 0; j < 4; j++) {
                int row = gm + wm * 64 + i * 16 + (lane >> 2);
                int col = gn + wn * 32 + j * 8 + ((lane & 3) << 1);
                float2 v0; v0.x = c[i][j][0]; v0.y = c[i][j][1];
                float2 v1; v1.x = c[i][j][2]; v1.y = c[i][j][3];
                *(float2*)(C + (size_t)row * ldc + col) = v0;
                *(float2*)(C + (size_t)(row + 8) * ldc + col) = v1;
            }
    }
}

// ---------------- softmax over rows of S (+ int32 bool-mask add) -> fp16 P ----------------
__global__ void softmax_k(const float* __restrict__ S, const int* __restrict__ mask,
                          __half* __restrict__ P) {
    int row = blockIdx.x;
    int b = row >> 11;
    const float* s = S + (size_t)row * SKL;
    const int* mk = mask + (size_t)b * SKL;
    int t = threadIdx.x;

    float vals[8];
    float mx = -3.4e38f;
#pragma unroll
    for (int i = 0; i < 8; i++) {
        int j = t + i * 256;
        float v = s[j] + (mk[j] ? 1.0f : 0.0f);
        vals[i] = v;
        mx = fmaxf(mx, v);
    }
    __shared__ float red[8];
#pragma unroll
    for (int o = 16; o > 0; o >>= 1) mx = fmaxf(mx, __shfl_xor_sync(0xffffffffu, mx, o));
    if ((t & 31) == 0) red[t >> 5] = mx;
    __syncthreads();
    if (t == 0) {
        float v = red[0];
        for (int i = 1; i < 8; i++) v = fmaxf(v, red[i]);
        red[0] = v;
    }
    __syncthreads();
    mx = red[0];

    float sum = 0.f;
#pragma unroll
    for (int i = 0; i < 8; i++) {
        vals[i] = __expf(vals[i] - mx);
        sum += vals[i];
    }
#pragma unroll
    for (int o = 16; o > 0; o >>= 1) sum += __shfl_xor_sync(0xffffffffu, sum, o);
    __syncthreads();
    if ((t & 31) == 0) red[t >> 5] = sum;
    __syncthreads();
    if (t == 0) {
        float v = 0.f;
        for (int i = 0; i < 8; i++) v += red[i];
        red[0] = v;
    }
    __syncthreads();
    float inv = 1.0f / red[0];
#pragma unroll
    for (int i = 0; i < 8; i++) {
        int j = t + i * 256;
        P[(size_t)row * SKL + j] = __float2half_rn(vals[i] * inv);
    }
}

// ---------------- launch ----------------
extern "C" void kernel_launch(void* const* d_in, const int* in_sizes, int n_in,
                              void* d_out, int out_size) {
    const float* q  = (const float*)d_in[0];
    const float* k  = (const float*)d_in[1];
    const float* v  = (const float*)d_in[2];
    const int*   mask = (const int*)d_in[3];
    const float* Wq = (const float*)d_in[4];
    const float* bq = (const float*)d_in[5];
    const float* Wk = (const float*)d_in[6];
    const float* bk = (const float*)d_in[7];
    const float* Wv = (const float*)d_in[8];
    const float* bv = (const float*)d_in[9];

    __half *qh, *ql, *kh, *kl, *vh, *vl;
    __half *Wqh, *Wql, *Wkh, *Wkl, *Wvh, *Wvl;
    __half *Qph, *Qpl, *Kph, *Kpl, *VpT, *P;
    float* S;
    cudaGetSymbolAddress((void**)&qh,  g_qh);  cudaGetSymbolAddress((void**)&ql,  g_ql);
    cudaGetSymbolAddress((void**)&kh,  g_kh);  cudaGetSymbolAddress((void**)&kl,  g_kl);
    cudaGetSymbolAddress((void**)&vh,  g_vh);  cudaGetSymbolAddress((void**)&vl,  g_vl);
    cudaGetSymbolAddress((void**)&Wqh, g_Wqh); cudaGetSymbolAddress((void**)&Wql, g_Wql);
    cudaGetSymbolAddress((void**)&Wkh, g_Wkh); cudaGetSymbolAddress((void**)&Wkl, g_Wkl);
    cudaGetSymbolAddress((void**)&Wvh, g_Wvh); cudaGetSymbolAddress((void**)&Wvl, g_Wvl);
    cudaGetSymbolAddress((void**)&Qph, g_Qph); cudaGetSymbolAddress((void**)&Qpl, g_Qpl);
    cudaGetSymbolAddress((void**)&Kph, g_Kph); cudaGetSymbolAddress((void**)&Kpl, g_Kpl);
    cudaGetSymbolAddress((void**)&VpT, g_VpT);
    cudaGetSymbolAddress((void**)&S,   g_S);
    cudaGetSymbolAddress((void**)&P,   g_P);

    const int SPLIT_SMEM = 2 * STG_S * (int)sizeof(__half);  // 81920 B
    cudaFuncSetAttribute(gemm_split<0>, cudaFuncAttributeMaxDynamicSharedMemorySize, SPLIT_SMEM);
    cudaFuncSetAttribute(gemm_split<1>, cudaFuncAttributeMaxDynamicSharedMemorySize, SPLIT_SMEM);
    cudaFuncSetAttribute(gemm_split<2>, cudaFuncAttributeMaxDynamicSharedMemorySize, SPLIT_SMEM);

    int n4 = BB * SQL * DDIM / 4;
    cvt_split<<<n4 / 256, 256>>>(q, qh, ql, n4);
    cvt_split<<<n4 / 256, 256>>>(k, kh, kl, n4);
    cvt_split<<<n4 / 256, 256>>>(v, vh, vl, n4);

    dim3 wtg(32, 32), wtb(32, 8);
    wtrans_split<<<wtg, wtb>>>(Wq, Wqh, Wql);
    wtrans_split<<<wtg, wtb>>>(Wk, Wkh, Wkl);
    wtrans_split<<<wtg, wtb>>>(Wv, Wvh, Wvl);

    // Projections: M = B*S = 16384, N = 1024, K = 1024 (3-pass split)
    gemm_split<0><<<dim3(8, 128, 1), 256, SPLIT_SMEM>>>(
        qh, ql, Wqh, Wql, Qph, Qpl, bq, 1024, 1024, 1024, 1024, 0, 0, 0);
    gemm_split<0><<<dim3(8, 128, 1), 256, SPLIT_SMEM>>>(
        kh, kl, Wkh, Wkl, Kph, Kpl, bk, 1024, 1024, 1024, 1024, 0, 0, 0);
    // V projection: tanh + transposed store into VpT[dv][b*SK+sk]
    gemm_split<1><<<dim3(8, 128, 1), 256, SPLIT_SMEM>>>(
        vh, vl, Wvh, Wvl, VpT, nullptr, bv, 1024, 1024, 1024, BB * SKL, 0, 0, 0);

    // Scores: per batch, S = Qp Kp^T  (M=N=2048, K=1024), 3-pass split
    gemm_split<2><<<dim3(16, 16, BB), 256, SPLIT_SMEM>>>(
        Qph, Qpl, Kph, Kpl, S, nullptr, nullptr, 1024, 1024, 1024, 2048,
        (long)SQL * DDIM, (long)SKL * DDIM, (long)SQL * SKL);

    // Softmax (+int mask) -> P fp16
    softmax_k<<<BB * SQL, 256>>>(S, mask, P);

    // Output: per batch, O = P · VpT^T  (M=2048, N=1024, K=2048), single-pass fp16
    gemm_f16<2><<<dim3(8, 16, BB), 256>>>(
        P, VpT, d_out, 2048, 2048, BB * SKL, 1024,
        (long)SQL * SKL, (long)SKL, (long)SQL * DDIM);
}